// round 1
// baseline (speedup 1.0000x reference)
#include <cuda_runtime.h>
#include <cuda_bf16.h>
#include <cstdint>

#define LEAKY 0.01f

static constexpr int MAX_N = 100000;
static constexpr int MAX_E = 1600000;

// Scratch (module-scope device globals; allocation inside kernel_launch is forbidden)
__device__ float g_h[(size_t)MAX_N * 128];    // GEMM output / gather source
__device__ float g_agg[(size_t)MAX_N * 128];  // scatter destination / next GEMM input
__device__ float g_rs_out[MAX_N];             // rsqrt(max(out_deg,1))
__device__ float g_rs_in[MAX_N];              // rsqrt(max(in_deg,1))

__device__ __forceinline__ float lrelu(float t) {
    return (t >= 0.f) ? t : LEAKY * t;
}

// ---------------------------------------------------------------------------
// Degree computation
// ---------------------------------------------------------------------------
__global__ void deg_kernel(const int* __restrict__ src, const int* __restrict__ dst,
                           float* __restrict__ dout, float* __restrict__ din, int E) {
    int i = blockIdx.x * blockDim.x + threadIdx.x;
    if (i < E) {
        atomicAdd(&dout[src[i]], 1.0f);
        atomicAdd(&din[dst[i]], 1.0f);
    }
}

__global__ void rsqrt_kernel(float* __restrict__ dout, float* __restrict__ din, int N) {
    int i = blockIdx.x * blockDim.x + threadIdx.x;
    if (i < N) {
        dout[i] = rsqrtf(fmaxf(dout[i], 1.0f));
        din[i]  = rsqrtf(fmaxf(din[i],  1.0f));
    }
}

// ---------------------------------------------------------------------------
// GEMM: out[N,BN] = pre(A)[N,K] @ W[K,BN]
//   FIRST=true :  pre(a)      = a * rs_out[row]
//   FIRST=false:  pre(a)      = lrelu(a * rs_in[row] + bprev[k]) * rs_out[row]
// (fuses the previous layer's epilogue + this layer's out-degree pre-scale)
// ---------------------------------------------------------------------------
template<int K, int BN, bool FIRST>
__global__ __launch_bounds__(256)
void gemm_kernel(const float* __restrict__ A, const float* __restrict__ W,
                 const float* __restrict__ bprev,
                 const float* __restrict__ rs_out, const float* __restrict__ rs_in,
                 float* __restrict__ out, int nrows)
{
    constexpr int BM = 128, BK = 32, TM = 8;
    constexpr int TN = BN / 16;
    constexpr int PAD = 4;

    __shared__ __align__(16) float As[BM][BK + PAD];
    __shared__ __align__(16) float Ws[BK][BN];

    const int tid = threadIdx.x;
    const int tx = tid & 15;
    const int ty = tid >> 4;
    const int rowBase = blockIdx.x * BM;

    float acc[TM][TN];
#pragma unroll
    for (int i = 0; i < TM; i++)
#pragma unroll
        for (int j = 0; j < TN; j++) acc[i][j] = 0.f;

    for (int k0 = 0; k0 < K; k0 += BK) {
        // ---- fill A tile (BM x BK), 4 float4 per thread, with fused epilogue ----
#pragma unroll
        for (int i = 0; i < 4; i++) {
            int lin = tid + i * 256;          // 0..1023 float4 slots
            int r   = lin >> 3;               // 0..127
            int kq  = lin & 7;                // 0..7 (quad within BK)
            int row = rowBase + r;
            float4 v = make_float4(0.f, 0.f, 0.f, 0.f);
            if (row < nrows) {
                v = *(const float4*)(A + (size_t)row * K + k0 + kq * 4);
                if (FIRST) {
                    float ro = rs_out[row];
                    v.x *= ro; v.y *= ro; v.z *= ro; v.w *= ro;
                } else {
                    float ri = rs_in[row];
                    float ro = rs_out[row];
                    int kk = k0 + kq * 4;
                    v.x = lrelu(fmaf(v.x, ri, bprev[kk + 0])) * ro;
                    v.y = lrelu(fmaf(v.y, ri, bprev[kk + 1])) * ro;
                    v.z = lrelu(fmaf(v.z, ri, bprev[kk + 2])) * ro;
                    v.w = lrelu(fmaf(v.w, ri, bprev[kk + 3])) * ro;
                }
            }
            *(float4*)(&As[r][kq * 4]) = v;
        }
        // ---- fill W tile (BK x BN) ----
        constexpr int W4 = (BK * BN) / 1024;  // float4 per thread
#pragma unroll
        for (int i = 0; i < W4; i++) {
            int lin = tid + i * 256;
            int k   = lin / (BN / 4);
            int nq  = lin % (BN / 4);
            float4 w = *(const float4*)(W + (size_t)(k0 + k) * BN + nq * 4);
            *(float4*)(&Ws[k][nq * 4]) = w;
        }
        __syncthreads();

        // ---- compute ----
#pragma unroll
        for (int k = 0; k < BK; k++) {
            float a[TM];
#pragma unroll
            for (int i = 0; i < TM; i++) a[i] = As[ty * TM + i][k];
            float w[TN];
#pragma unroll
            for (int j = 0; j < TN; j += 4) {
                float4 wv = *(const float4*)(&Ws[k][tx * TN + j]);
                w[j + 0] = wv.x; w[j + 1] = wv.y; w[j + 2] = wv.z; w[j + 3] = wv.w;
            }
#pragma unroll
            for (int i = 0; i < TM; i++)
#pragma unroll
                for (int j = 0; j < TN; j++)
                    acc[i][j] = fmaf(a[i], w[j], acc[i][j]);
        }
        __syncthreads();
    }

    // ---- store ----
#pragma unroll
    for (int i = 0; i < TM; i++) {
        int row = rowBase + ty * TM + i;
        if (row < nrows) {
#pragma unroll
            for (int j = 0; j < TN; j += 4) {
                float4 v = make_float4(acc[i][j], acc[i][j + 1], acc[i][j + 2], acc[i][j + 3]);
                *(float4*)(out + (size_t)row * BN + tx * TN + j) = v;
            }
        }
    }
}

// ---------------------------------------------------------------------------
// Edge scatter: agg[dst[e]][:] += h[src[e]][:]   (F/4 lanes per edge, vec4 red)
// ---------------------------------------------------------------------------
template<int F>
__global__ void scatter_kernel(const int* __restrict__ src, const int* __restrict__ dst,
                               const float* __restrict__ h, float* __restrict__ agg, int E)
{
    constexpr int LPE = F / 4;  // lanes per edge (32 for F=128, 16 for F=64)
    int gtid = blockIdx.x * blockDim.x + threadIdx.x;
    int e = gtid / LPE;
    int l = gtid % LPE;
    if (e >= E) return;
    int s = src[e];
    int d = dst[e];
    float4 v = *(const float4*)(h + (size_t)s * F + l * 4);
    float* p = agg + (size_t)d * F + l * 4;
    asm volatile("red.global.add.v4.f32 [%0], {%1,%2,%3,%4};"
                 :: "l"(p), "f"(v.x), "f"(v.y), "f"(v.z), "f"(v.w) : "memory");
}

// ---------------------------------------------------------------------------
// Final epilogue: out = lrelu(agg * rs_in + b2), F = 64
// ---------------------------------------------------------------------------
__global__ void epilogue_kernel(const float* __restrict__ agg, const float* __restrict__ rs_in,
                                const float* __restrict__ b, float* __restrict__ out, int N)
{
    int idx = blockIdx.x * blockDim.x + threadIdx.x;  // one float4 each
    int total = N * 16;                                // N*64/4
    if (idx >= total) return;
    int row = idx >> 4;
    int c = (idx & 15) * 4;
    float ri = rs_in[row];
    float4 v = *(const float4*)(agg + (size_t)row * 64 + c);
    v.x = lrelu(fmaf(v.x, ri, b[c + 0]));
    v.y = lrelu(fmaf(v.y, ri, b[c + 1]));
    v.z = lrelu(fmaf(v.z, ri, b[c + 2]));
    v.w = lrelu(fmaf(v.w, ri, b[c + 3]));
    *(float4*)(out + (size_t)row * 64 + c) = v;
}

// ---------------------------------------------------------------------------
// Launch
// ---------------------------------------------------------------------------
static inline int cdiv(int a, int b) { return (a + b - 1) / b; }

extern "C" void kernel_launch(void* const* d_in, const int* in_sizes, int n_in,
                              void* d_out, int out_size)
{
    const float* n_feat = (const float*)d_in[0];
    const int*   src    = (const int*)  d_in[1];
    const int*   dst    = (const int*)  d_in[2];
    const float* W0     = (const float*)d_in[3];
    const float* b0     = (const float*)d_in[4];
    const float* W1     = (const float*)d_in[5];
    const float* b1     = (const float*)d_in[6];
    const float* W2     = (const float*)d_in[7];
    const float* b2     = (const float*)d_in[8];
    float* out = (float*)d_out;

    const int N = in_sizes[0] / 128;
    const int E = in_sizes[1];

    float *d_h, *d_agg, *d_rso, *d_rsi;
    cudaGetSymbolAddress((void**)&d_h,   g_h);
    cudaGetSymbolAddress((void**)&d_agg, g_agg);
    cudaGetSymbolAddress((void**)&d_rso, g_rs_out);
    cudaGetSymbolAddress((void**)&d_rsi, g_rs_in);

    // --- degrees ---
    cudaMemsetAsync(d_rso, 0, (size_t)N * sizeof(float));
    cudaMemsetAsync(d_rsi, 0, (size_t)N * sizeof(float));
    deg_kernel<<<cdiv(E, 256), 256>>>(src, dst, d_rso, d_rsi, E);
    rsqrt_kernel<<<cdiv(N, 256), 256>>>(d_rso, d_rsi, N);

    const int gemm_blocks = cdiv(N, 128);

    // --- layer 0: 128 -> 128 ---
    gemm_kernel<128, 128, true><<<gemm_blocks, 256>>>(n_feat, W0, nullptr, d_rso, d_rsi, d_h, N);
    cudaMemsetAsync(d_agg, 0, (size_t)N * 128 * sizeof(float));
    scatter_kernel<128><<<cdiv(E * 32, 256), 256>>>(src, dst, d_h, d_agg, E);

    // --- layer 1: 128 -> 64 (epilogue of layer 0 fused into A load) ---
    gemm_kernel<128, 64, false><<<gemm_blocks, 256>>>(d_agg, W1, b0, d_rso, d_rsi, d_h, N);
    cudaMemsetAsync(d_agg, 0, (size_t)N * 64 * sizeof(float));
    scatter_kernel<64><<<cdiv(E * 16, 256), 256>>>(src, dst, d_h, d_agg, E);

    // --- layer 2: 64 -> 64 (epilogue of layer 1 fused into A load) ---
    gemm_kernel<64, 64, false><<<gemm_blocks, 256>>>(d_agg, W2, b1, d_rso, d_rsi, d_h, N);
    cudaMemsetAsync(d_agg, 0, (size_t)N * 64 * sizeof(float));
    scatter_kernel<64><<<cdiv(E * 16, 256), 256>>>(src, dst, d_h, d_agg, E);

    // --- final epilogue ---
    epilogue_kernel<<<cdiv(N * 16, 256), 256>>>(d_agg, d_rsi, b2, out, N);
}

// round 2
// speedup vs baseline: 1.6220x; 1.6220x over previous
#include <cuda_runtime.h>
#include <cuda_bf16.h>
#include <cstdint>

#define LEAKY 0.01f

static constexpr int MAX_N = 100000;
static constexpr int MAX_E = 1600000;

// Scratch (module-scope device globals; allocation inside kernel_launch is forbidden)
__device__ float g_h[(size_t)MAX_N * 128];    // GEMM output / gather source
__device__ float g_agg[(size_t)MAX_N * 128];  // gather destination / next GEMM input
__device__ float g_rs_out[MAX_N];             // rsqrt(max(out_deg,1))
__device__ float g_rs_in[MAX_N];              // rsqrt(max(in_deg,1))
__device__ int   g_indeg[MAX_N];              // int in-degree counts
__device__ int   g_excl[MAX_N];               // scan scratch
__device__ int   g_row_start[MAX_N + 1];      // CSR row offsets (by dst)
__device__ int   g_cursor[MAX_N];             // CSR fill cursors
__device__ int   g_csr_src[MAX_E];            // CSR column (src node) array
__device__ int   g_bsum[512];                 // scan block sums

__device__ __forceinline__ float lrelu(float t) {
    return (t >= 0.f) ? t : LEAKY * t;
}

// ---------------------------------------------------------------------------
// Degrees: float out-degree (atomic), int in-degree (atomic)
// ---------------------------------------------------------------------------
__global__ void deg_kernel(const int* __restrict__ src, const int* __restrict__ dst,
                           float* __restrict__ dout, int* __restrict__ indeg, int E) {
    int i = blockIdx.x * blockDim.x + threadIdx.x;
    if (i < E) {
        atomicAdd(&dout[src[i]], 1.0f);
        atomicAdd(&indeg[dst[i]], 1);
    }
}

__global__ void rsqrt_kernel(float* __restrict__ dout, const int* __restrict__ indeg,
                             float* __restrict__ rsin, int N) {
    int i = blockIdx.x * blockDim.x + threadIdx.x;
    if (i < N) {
        dout[i] = rsqrtf(fmaxf(dout[i], 1.0f));
        rsin[i] = rsqrtf(fmaxf((float)indeg[i], 1.0f));
    }
}

// ---------------------------------------------------------------------------
// Exclusive scan over in-degrees (3-kernel: block scan, block-sum scan, add)
// ---------------------------------------------------------------------------
__global__ void scan_block(const int* __restrict__ deg, int* __restrict__ excl,
                           int* __restrict__ bsum, int N) {
    __shared__ int ts[256];
    int tid = threadIdx.x;
    int base = blockIdx.x * 1024 + tid * 4;
    int v[4];
    int sum = 0;
#pragma unroll
    for (int i = 0; i < 4; i++) {
        int idx = base + i;
        v[i] = (idx < N) ? deg[idx] : 0;
        sum += v[i];
    }
    ts[tid] = sum;
    __syncthreads();
    for (int off = 1; off < 256; off <<= 1) {
        int t = (tid >= off) ? ts[tid - off] : 0;
        __syncthreads();
        ts[tid] += t;
        __syncthreads();
    }
    if (tid == 255) bsum[blockIdx.x] = ts[255];
    int run = ts[tid] - sum;  // exclusive prefix of this thread
#pragma unroll
    for (int i = 0; i < 4; i++) {
        int idx = base + i;
        if (idx < N) excl[idx] = run;
        run += v[i];
    }
}

__global__ void scan_bsum(int* __restrict__ bsum, int nb) {
    __shared__ int s[512];
    int tid = threadIdx.x;
    int v = (tid < nb) ? bsum[tid] : 0;
    s[tid] = v;
    __syncthreads();
    for (int off = 1; off < 512; off <<= 1) {
        int t = (tid >= off) ? s[tid - off] : 0;
        __syncthreads();
        s[tid] += t;
        __syncthreads();
    }
    if (tid < nb) bsum[tid] = s[tid] - v;  // exclusive
}

__global__ void scan_add(const int* __restrict__ excl, const int* __restrict__ bsum,
                         int* __restrict__ row_start, int* __restrict__ cursor,
                         int N, int E) {
    int i = blockIdx.x * blockDim.x + threadIdx.x;
    if (i < N) {
        int v = excl[i] + bsum[i >> 10];
        row_start[i] = v;
        cursor[i] = v;
    }
    if (i == 0) row_start[N] = E;
}

__global__ void fill_csr(const int* __restrict__ src, const int* __restrict__ dst,
                         int* __restrict__ cursor, int* __restrict__ csr_src, int E) {
    int e = blockIdx.x * blockDim.x + threadIdx.x;
    if (e < E) {
        int pos = atomicAdd(&cursor[dst[e]], 1);
        csr_src[pos] = src[e];
    }
}

// ---------------------------------------------------------------------------
// GEMM: out[N,BN] = pre(A)[N,K] @ W[K,BN]
//   FIRST=true :  pre(a) = a * rs_out[row]
//   FIRST=false:  pre(a) = lrelu(a * rs_in[row] + bprev[k]) * rs_out[row]
// ---------------------------------------------------------------------------
template<int K, int BN, bool FIRST>
__global__ __launch_bounds__(256)
void gemm_kernel(const float* __restrict__ A, const float* __restrict__ W,
                 const float* __restrict__ bprev,
                 const float* __restrict__ rs_out, const float* __restrict__ rs_in,
                 float* __restrict__ out, int nrows)
{
    constexpr int BM = 128, BK = 32, TM = 8;
    constexpr int TN = BN / 16;
    constexpr int PAD = 4;

    __shared__ __align__(16) float As[BM][BK + PAD];
    __shared__ __align__(16) float Ws[BK][BN];

    const int tid = threadIdx.x;
    const int tx = tid & 15;
    const int ty = tid >> 4;
    const int rowBase = blockIdx.x * BM;

    float acc[TM][TN];
#pragma unroll
    for (int i = 0; i < TM; i++)
#pragma unroll
        for (int j = 0; j < TN; j++) acc[i][j] = 0.f;

    for (int k0 = 0; k0 < K; k0 += BK) {
#pragma unroll
        for (int i = 0; i < 4; i++) {
            int lin = tid + i * 256;
            int r   = lin >> 3;
            int kq  = lin & 7;
            int row = rowBase + r;
            float4 v = make_float4(0.f, 0.f, 0.f, 0.f);
            if (row < nrows) {
                v = *(const float4*)(A + (size_t)row * K + k0 + kq * 4);
                if (FIRST) {
                    float ro = rs_out[row];
                    v.x *= ro; v.y *= ro; v.z *= ro; v.w *= ro;
                } else {
                    float ri = rs_in[row];
                    float ro = rs_out[row];
                    int kk = k0 + kq * 4;
                    v.x = lrelu(fmaf(v.x, ri, bprev[kk + 0])) * ro;
                    v.y = lrelu(fmaf(v.y, ri, bprev[kk + 1])) * ro;
                    v.z = lrelu(fmaf(v.z, ri, bprev[kk + 2])) * ro;
                    v.w = lrelu(fmaf(v.w, ri, bprev[kk + 3])) * ro;
                }
            }
            *(float4*)(&As[r][kq * 4]) = v;
        }
        constexpr int W4 = (BK * BN) / 1024;
#pragma unroll
        for (int i = 0; i < W4; i++) {
            int lin = tid + i * 256;
            int k   = lin / (BN / 4);
            int nq  = lin % (BN / 4);
            float4 w = *(const float4*)(W + (size_t)(k0 + k) * BN + nq * 4);
            *(float4*)(&Ws[k][nq * 4]) = w;
        }
        __syncthreads();

#pragma unroll
        for (int k = 0; k < BK; k++) {
            float a[TM];
#pragma unroll
            for (int i = 0; i < TM; i++) a[i] = As[ty * TM + i][k];
            float w[TN];
#pragma unroll
            for (int j = 0; j < TN; j += 4) {
                float4 wv = *(const float4*)(&Ws[k][tx * TN + j]);
                w[j + 0] = wv.x; w[j + 1] = wv.y; w[j + 2] = wv.z; w[j + 3] = wv.w;
            }
#pragma unroll
            for (int i = 0; i < TM; i++)
#pragma unroll
                for (int j = 0; j < TN; j++)
                    acc[i][j] = fmaf(a[i], w[j], acc[i][j]);
        }
        __syncthreads();
    }

#pragma unroll
    for (int i = 0; i < TM; i++) {
        int row = rowBase + ty * TM + i;
        if (row < nrows) {
#pragma unroll
            for (int j = 0; j < TN; j += 4) {
                float4 v = make_float4(acc[i][j], acc[i][j + 1], acc[i][j + 2], acc[i][j + 3]);
                *(float4*)(out + (size_t)row * BN + tx * TN + j) = v;
            }
        }
    }
}

// ---------------------------------------------------------------------------
// CSR gather aggregation: agg[n][:] = sum_{e in-edges(n)} h[csr_src[e]][:]
// One warp per node. F=128: lane owns 4 cols (float4). F=64: 2 cols (float2).
// ---------------------------------------------------------------------------
__global__ __launch_bounds__(256)
void gather128(const int* __restrict__ row_start, const int* __restrict__ csr,
               const float* __restrict__ h, float* __restrict__ agg, int N)
{
    int warp = (blockIdx.x * blockDim.x + threadIdx.x) >> 5;
    int lane = threadIdx.x & 31;
    if (warp >= N) return;
    int start = row_start[warp];
    int end   = row_start[warp + 1];
    float4 acc = make_float4(0.f, 0.f, 0.f, 0.f);
    int j = start;
    for (; j + 1 < end; j += 2) {
        int s0 = __ldg(&csr[j]);
        int s1 = __ldg(&csr[j + 1]);
        float4 v0 = *(const float4*)(h + (size_t)s0 * 128 + lane * 4);
        float4 v1 = *(const float4*)(h + (size_t)s1 * 128 + lane * 4);
        acc.x += v0.x + v1.x;
        acc.y += v0.y + v1.y;
        acc.z += v0.z + v1.z;
        acc.w += v0.w + v1.w;
    }
    if (j < end) {
        int s0 = __ldg(&csr[j]);
        float4 v0 = *(const float4*)(h + (size_t)s0 * 128 + lane * 4);
        acc.x += v0.x; acc.y += v0.y; acc.z += v0.z; acc.w += v0.w;
    }
    *(float4*)(agg + (size_t)warp * 128 + lane * 4) = acc;
}

__global__ __launch_bounds__(256)
void gather64(const int* __restrict__ row_start, const int* __restrict__ csr,
              const float* __restrict__ h, float* __restrict__ agg, int N)
{
    int warp = (blockIdx.x * blockDim.x + threadIdx.x) >> 5;
    int lane = threadIdx.x & 31;
    if (warp >= N) return;
    int start = row_start[warp];
    int end   = row_start[warp + 1];
    float2 acc = make_float2(0.f, 0.f);
    int j = start;
    for (; j + 1 < end; j += 2) {
        int s0 = __ldg(&csr[j]);
        int s1 = __ldg(&csr[j + 1]);
        float2 v0 = *(const float2*)(h + (size_t)s0 * 64 + lane * 2);
        float2 v1 = *(const float2*)(h + (size_t)s1 * 64 + lane * 2);
        acc.x += v0.x + v1.x;
        acc.y += v0.y + v1.y;
    }
    if (j < end) {
        int s0 = __ldg(&csr[j]);
        float2 v0 = *(const float2*)(h + (size_t)s0 * 64 + lane * 2);
        acc.x += v0.x; acc.y += v0.y;
    }
    *(float2*)(agg + (size_t)warp * 64 + lane * 2) = acc;
}

// ---------------------------------------------------------------------------
// Final epilogue: out = lrelu(agg * rs_in + b2), F = 64
// ---------------------------------------------------------------------------
__global__ void epilogue_kernel(const float* __restrict__ agg, const float* __restrict__ rs_in,
                                const float* __restrict__ b, float* __restrict__ out, int N)
{
    int idx = blockIdx.x * blockDim.x + threadIdx.x;
    int total = N * 16;
    if (idx >= total) return;
    int row = idx >> 4;
    int c = (idx & 15) * 4;
    float ri = rs_in[row];
    float4 v = *(const float4*)(agg + (size_t)row * 64 + c);
    v.x = lrelu(fmaf(v.x, ri, b[c + 0]));
    v.y = lrelu(fmaf(v.y, ri, b[c + 1]));
    v.z = lrelu(fmaf(v.z, ri, b[c + 2]));
    v.w = lrelu(fmaf(v.w, ri, b[c + 3]));
    *(float4*)(out + (size_t)row * 64 + c) = v;
}

// ---------------------------------------------------------------------------
// Launch
// ---------------------------------------------------------------------------
static inline int cdiv(int a, int b) { return (a + b - 1) / b; }

extern "C" void kernel_launch(void* const* d_in, const int* in_sizes, int n_in,
                              void* d_out, int out_size)
{
    const float* n_feat = (const float*)d_in[0];
    const int*   src    = (const int*)  d_in[1];
    const int*   dst    = (const int*)  d_in[2];
    const float* W0     = (const float*)d_in[3];
    const float* b0     = (const float*)d_in[4];
    const float* W1     = (const float*)d_in[5];
    const float* b1     = (const float*)d_in[6];
    const float* W2     = (const float*)d_in[7];
    const float* b2     = (const float*)d_in[8];
    float* out = (float*)d_out;

    const int N = in_sizes[0] / 128;
    const int E = in_sizes[1];

    float *d_h, *d_agg, *d_rso, *d_rsi;
    int *d_indeg, *d_excl, *d_rs, *d_cur, *d_csr, *d_bsum;
    cudaGetSymbolAddress((void**)&d_h,    g_h);
    cudaGetSymbolAddress((void**)&d_agg,  g_agg);
    cudaGetSymbolAddress((void**)&d_rso,  g_rs_out);
    cudaGetSymbolAddress((void**)&d_rsi,  g_rs_in);
    cudaGetSymbolAddress((void**)&d_indeg, g_indeg);
    cudaGetSymbolAddress((void**)&d_excl, g_excl);
    cudaGetSymbolAddress((void**)&d_rs,   g_row_start);
    cudaGetSymbolAddress((void**)&d_cur,  g_cursor);
    cudaGetSymbolAddress((void**)&d_csr,  g_csr_src);
    cudaGetSymbolAddress((void**)&d_bsum, g_bsum);

    // --- degrees ---
    cudaMemsetAsync(d_rso, 0, (size_t)N * sizeof(float));
    cudaMemsetAsync(d_indeg, 0, (size_t)N * sizeof(int));
    deg_kernel<<<cdiv(E, 256), 256>>>(src, dst, d_rso, d_indeg, E);
    rsqrt_kernel<<<cdiv(N, 256), 256>>>(d_rso, d_indeg, d_rsi, N);

    // --- CSR build (once, reused by all 3 layers) ---
    const int nb = cdiv(N, 1024);
    scan_block<<<nb, 256>>>(d_indeg, d_excl, d_bsum, N);
    scan_bsum<<<1, 512>>>(d_bsum, nb);
    scan_add<<<cdiv(N, 256), 256>>>(d_excl, d_bsum, d_rs, d_cur, N, E);
    fill_csr<<<cdiv(E, 256), 256>>>(src, dst, d_cur, d_csr, E);

    const int gemm_blocks = cdiv(N, 128);
    const int gw_blocks = cdiv(N, 8);  // gather: 8 warps/block

    // --- layer 0: 128 -> 128 ---
    gemm_kernel<128, 128, true><<<gemm_blocks, 256>>>(n_feat, W0, nullptr, d_rso, d_rsi, d_h, N);
    gather128<<<gw_blocks, 256>>>(d_rs, d_csr, d_h, d_agg, N);

    // --- layer 1: 128 -> 64 (layer-0 epilogue fused into A load) ---
    gemm_kernel<128, 64, false><<<gemm_blocks, 256>>>(d_agg, W1, b0, d_rso, d_rsi, d_h, N);
    gather64<<<gw_blocks, 256>>>(d_rs, d_csr, d_h, d_agg, N);

    // --- layer 2: 64 -> 64 (layer-1 epilogue fused into A load) ---
    gemm_kernel<64, 64, false><<<gemm_blocks, 256>>>(d_agg, W2, b1, d_rso, d_rsi, d_h, N);
    gather64<<<gw_blocks, 256>>>(d_rs, d_csr, d_h, d_agg, N);

    // --- final epilogue ---
    epilogue_kernel<<<cdiv(N * 16, 256), 256>>>(d_agg, d_rsi, b2, out, N);
}

// round 4
// speedup vs baseline: 1.8574x; 1.1451x over previous
#include <cuda_runtime.h>
#include <cuda_bf16.h>
#include <cstdint>

#define LEAKY 0.01f

static constexpr int MAX_N = 100000;
static constexpr int MAX_E = 1600000;

// Scratch (module-scope device globals; allocation inside kernel_launch is forbidden)
__device__ float    g_h[(size_t)MAX_N * 128];    // GEMM output / gather source
__device__ float    g_agg[(size_t)MAX_N * 128];  // gather destination / next GEMM input
__device__ float    g_rs_out[MAX_N];             // rsqrt(max(out_deg,1))
__device__ float    g_rs_in[MAX_N];              // rsqrt(max(in_deg,1))
__device__ int      g_indeg[MAX_N];              // int in-degree counts
__device__ int      g_excl[MAX_N];               // scan scratch
__device__ int      g_row_start[MAX_N + 1];      // CSR row offsets (by dst)
__device__ int      g_cursor[MAX_N];             // CSR fill cursors
__device__ int      g_csr_src[MAX_E];            // CSR column (src node) array
__device__ int      g_bsum[512];                 // scan block sums
__device__ uint32_t g_bt_hi[128 * 128];          // W^T tf32-hi [n][k]
__device__ uint32_t g_bt_lo[128 * 128];          // W^T tf32-lo [n][k]

__device__ __forceinline__ float lrelu(float t) {
    return (t >= 0.f) ? t : LEAKY * t;
}

__device__ __forceinline__ uint32_t f2tf32(float x) {
    uint32_t r;
    asm("cvt.rna.tf32.f32 %0, %1;" : "=r"(r) : "f"(x));
    return r;
}

__device__ __forceinline__ void mma_tf32(float* d, const uint32_t* a, const uint32_t* b) {
    asm volatile(
        "mma.sync.aligned.m16n8k8.row.col.f32.tf32.tf32.f32 "
        "{%0,%1,%2,%3}, {%4,%5,%6,%7}, {%8,%9}, {%0,%1,%2,%3};"
        : "+f"(d[0]), "+f"(d[1]), "+f"(d[2]), "+f"(d[3])
        : "r"(a[0]), "r"(a[1]), "r"(a[2]), "r"(a[3]), "r"(b[0]), "r"(b[1]));
}

// ---------------------------------------------------------------------------
// Degrees
// ---------------------------------------------------------------------------
__global__ void deg_kernel(const int* __restrict__ src, const int* __restrict__ dst,
                           float* __restrict__ dout, int* __restrict__ indeg, int E) {
    int i = blockIdx.x * blockDim.x + threadIdx.x;
    if (i < E) {
        atomicAdd(&dout[src[i]], 1.0f);
        atomicAdd(&indeg[dst[i]], 1);
    }
}

__global__ void rsqrt_kernel(float* __restrict__ dout, const int* __restrict__ indeg,
                             float* __restrict__ rsin, int N) {
    int i = blockIdx.x * blockDim.x + threadIdx.x;
    if (i < N) {
        dout[i] = rsqrtf(fmaxf(dout[i], 1.0f));
        rsin[i] = rsqrtf(fmaxf((float)indeg[i], 1.0f));
    }
}

// ---------------------------------------------------------------------------
// Exclusive scan over in-degrees
// ---------------------------------------------------------------------------
__global__ void scan_block(const int* __restrict__ deg, int* __restrict__ excl,
                           int* __restrict__ bsum, int N) {
    __shared__ int ts[256];
    int tid = threadIdx.x;
    int base = blockIdx.x * 1024 + tid * 4;
    int v[4];
    int sum = 0;
#pragma unroll
    for (int i = 0; i < 4; i++) {
        int idx = base + i;
        v[i] = (idx < N) ? deg[idx] : 0;
        sum += v[i];
    }
    ts[tid] = sum;
    __syncthreads();
    for (int off = 1; off < 256; off <<= 1) {
        int t = (tid >= off) ? ts[tid - off] : 0;
        __syncthreads();
        ts[tid] += t;
        __syncthreads();
    }
    if (tid == 255) bsum[blockIdx.x] = ts[255];
    int run = ts[tid] - sum;
#pragma unroll
    for (int i = 0; i < 4; i++) {
        int idx = base + i;
        if (idx < N) excl[idx] = run;
        run += v[i];
    }
}

__global__ void scan_bsum(int* __restrict__ bsum, int nb) {
    __shared__ int s[512];
    int tid = threadIdx.x;
    int v = (tid < nb) ? bsum[tid] : 0;
    s[tid] = v;
    __syncthreads();
    for (int off = 1; off < 512; off <<= 1) {
        int t = (tid >= off) ? s[tid - off] : 0;
        __syncthreads();
        s[tid] += t;
        __syncthreads();
    }
    if (tid < nb) bsum[tid] = s[tid] - v;
}

__global__ void scan_add(const int* __restrict__ excl, const int* __restrict__ bsum,
                         int* __restrict__ row_start, int* __restrict__ cursor,
                         int N, int E) {
    int i = blockIdx.x * blockDim.x + threadIdx.x;
    if (i < N) {
        int v = excl[i] + bsum[i >> 10];
        row_start[i] = v;
        cursor[i] = v;
    }
    if (i == 0) row_start[N] = E;
}

__global__ void fill_csr(const int* __restrict__ src, const int* __restrict__ dst,
                         int* __restrict__ cursor, int* __restrict__ csr_src, int E) {
    int e = blockIdx.x * blockDim.x + threadIdx.x;
    if (e < E) {
        int pos = atomicAdd(&cursor[dst[e]], 1);
        csr_src[pos] = src[e];
    }
}

// ---------------------------------------------------------------------------
// W split: Bt_hi/lo[n*K + k] = tf32 split of W[k*BN + n]  (transpose + convert)
// ---------------------------------------------------------------------------
__global__ void split_w(const float* __restrict__ W, uint32_t* __restrict__ bt_hi,
                        uint32_t* __restrict__ bt_lo, int K, int BN) {
    int idx = blockIdx.x * blockDim.x + threadIdx.x;
    if (idx >= K * BN) return;
    int k = idx / BN;
    int n = idx % BN;
    float w = W[idx];
    uint32_t hi = f2tf32(w);
    uint32_t lo = f2tf32(w - __uint_as_float(hi));
    bt_hi[n * K + k] = hi;
    bt_lo[n * K + k] = lo;
}

// ---------------------------------------------------------------------------
// TF32 mma.sync GEMM (3xTF32 split): out[N,BN] = pre(A)[N,K] @ W[K,BN]
//   FIRST=true :  pre(a) = a * rs_out[row]
//   FIRST=false:  pre(a) = lrelu(a * rs_in[row] + bprev[k]) * rs_out[row]
// Bt = W^T pre-split (hi/lo tf32), layout [BN][K].
// Block: 256 threads (8 warps), BM=128 rows, full BN, BK=32 chunks.
// ---------------------------------------------------------------------------
template<int K, int BN, bool FIRST>
__global__ __launch_bounds__(256)
void gemm_mma(const float* __restrict__ A,
              const uint32_t* __restrict__ Bt_hi, const uint32_t* __restrict__ Bt_lo,
              const float* __restrict__ bprev,
              const float* __restrict__ rs_out, const float* __restrict__ rs_in,
              float* __restrict__ out, int nrows)
{
    constexpr int WARPS_M = (BN == 128) ? 2 : 4;
    constexpr int WARPS_N = 8 / WARPS_M;
    constexpr int WM = 128 / WARPS_M;   // 64 or 32
    constexpr int WN = BN / WARPS_N;    // 32
    constexpr int MF = WM / 16;         // 4 or 2
    constexpr int NF = WN / 8;          // 4
    constexpr int STRIDE = 36;          // 32 + 4 pad (words)

    extern __shared__ __align__(16) uint32_t smemw[];
    uint32_t* As_hi = smemw;                       // [128][36]
    uint32_t* As_lo = As_hi + 128 * STRIDE;
    uint32_t* Bs_hi = As_lo + 128 * STRIDE;        // [BN][36]
    uint32_t* Bs_lo = Bs_hi + BN * STRIDE;

    const int tid = threadIdx.x;
    const int wid = tid >> 5;
    const int lane = tid & 31;
    const int wm = wid % WARPS_M;
    const int wn = wid / WARPS_M;
    const int rowBase = blockIdx.x * 128;
    const int g = lane >> 2;   // group id 0..7
    const int t4 = lane & 3;   // thread in group 0..3

    float acc[MF][NF][4];
#pragma unroll
    for (int i = 0; i < MF; i++)
#pragma unroll
        for (int j = 0; j < NF; j++)
#pragma unroll
            for (int c = 0; c < 4; c++) acc[i][j][c] = 0.f;

    for (int k0 = 0; k0 < K; k0 += 32) {
        // ---- A tile: 1024 float4 slots, 4/thread, fused epilogue + tf32 split ----
#pragma unroll
        for (int i = 0; i < 4; i++) {
            int lin = tid + i * 256;
            int r = lin >> 3;
            int kq = lin & 7;
            int row = rowBase + r;
            float4 v = make_float4(0.f, 0.f, 0.f, 0.f);
            if (row < nrows) {
                v = *(const float4*)(A + (size_t)row * K + k0 + kq * 4);
                if (FIRST) {
                    float ro = rs_out[row];
                    v.x *= ro; v.y *= ro; v.z *= ro; v.w *= ro;
                } else {
                    float ri = rs_in[row];
                    float ro = rs_out[row];
                    int kk = k0 + kq * 4;
                    v.x = lrelu(fmaf(v.x, ri, bprev[kk + 0])) * ro;
                    v.y = lrelu(fmaf(v.y, ri, bprev[kk + 1])) * ro;
                    v.z = lrelu(fmaf(v.z, ri, bprev[kk + 2])) * ro;
                    v.w = lrelu(fmaf(v.w, ri, bprev[kk + 3])) * ro;
                }
            }
            uint4 hi, lo;
            hi.x = f2tf32(v.x); lo.x = f2tf32(v.x - __uint_as_float(hi.x));
            hi.y = f2tf32(v.y); lo.y = f2tf32(v.y - __uint_as_float(hi.y));
            hi.z = f2tf32(v.z); lo.z = f2tf32(v.z - __uint_as_float(hi.z));
            hi.w = f2tf32(v.w); lo.w = f2tf32(v.w - __uint_as_float(hi.w));
            *(uint4*)(As_hi + r * STRIDE + kq * 4) = hi;
            *(uint4*)(As_lo + r * STRIDE + kq * 4) = lo;
        }
        // ---- B tile: BN*8 float4 slots, pre-split global -> SMEM ----
        constexpr int BSLOTS = BN * 8;
        constexpr int BPER = BSLOTS / 256;
#pragma unroll
        for (int i = 0; i < BPER; i++) {
            int lin = tid + i * 256;
            int n = lin >> 3;
            int q = lin & 7;
            uint4 hv = *(const uint4*)(Bt_hi + (size_t)n * K + k0 + q * 4);
            uint4 lv = *(const uint4*)(Bt_lo + (size_t)n * K + k0 + q * 4);
            *(uint4*)(Bs_hi + n * STRIDE + q * 4) = hv;
            *(uint4*)(Bs_lo + n * STRIDE + q * 4) = lv;
        }
        __syncthreads();

        // ---- compute: 4 k-steps of 8 ----
#pragma unroll
        for (int ks = 0; ks < 4; ks++) {
            const int kk = ks * 8;
            uint32_t ah[MF][4], al[MF][4];
#pragma unroll
            for (int mf = 0; mf < MF; mf++) {
                int r = wm * WM + mf * 16 + g;
                int c = kk + t4;
                ah[mf][0] = As_hi[r * STRIDE + c];
                ah[mf][1] = As_hi[(r + 8) * STRIDE + c];
                ah[mf][2] = As_hi[r * STRIDE + c + 4];
                ah[mf][3] = As_hi[(r + 8) * STRIDE + c + 4];
                al[mf][0] = As_lo[r * STRIDE + c];
                al[mf][1] = As_lo[(r + 8) * STRIDE + c];
                al[mf][2] = As_lo[r * STRIDE + c + 4];
                al[mf][3] = As_lo[(r + 8) * STRIDE + c + 4];
            }
            uint32_t bh[NF][2], bl[NF][2];
#pragma unroll
            for (int nf = 0; nf < NF; nf++) {
                int n = wn * WN + nf * 8 + g;
                int k = kk + t4;
                bh[nf][0] = Bs_hi[n * STRIDE + k];
                bh[nf][1] = Bs_hi[n * STRIDE + k + 4];
                bl[nf][0] = Bs_lo[n * STRIDE + k];
                bl[nf][1] = Bs_lo[n * STRIDE + k + 4];
            }
#pragma unroll
            for (int mf = 0; mf < MF; mf++)
#pragma unroll
                for (int nf = 0; nf < NF; nf++) {
                    mma_tf32(acc[mf][nf], ah[mf], bh[nf]);
                    mma_tf32(acc[mf][nf], al[mf], bh[nf]);
                    mma_tf32(acc[mf][nf], ah[mf], bl[nf]);
                }
        }
        __syncthreads();
    }

    // ---- store: per frag, rows g and g+8, cols 2*t4, 2*t4+1 ----
#pragma unroll
    for (int mf = 0; mf < MF; mf++) {
#pragma unroll
        for (int nf = 0; nf < NF; nf++) {
            int r0 = rowBase + wm * WM + mf * 16 + g;
            int col = wn * WN + nf * 8 + t4 * 2;
            if (r0 < nrows)
                *(float2*)(out + (size_t)r0 * BN + col) =
                    make_float2(acc[mf][nf][0], acc[mf][nf][1]);
            if (r0 + 8 < nrows)
                *(float2*)(out + (size_t)(r0 + 8) * BN + col) =
                    make_float2(acc[mf][nf][2], acc[mf][nf][3]);
        }
    }
}

// ---------------------------------------------------------------------------
// CSR gather aggregation
// ---------------------------------------------------------------------------
__global__ __launch_bounds__(256)
void gather128(const int* __restrict__ row_start, const int* __restrict__ csr,
               const float* __restrict__ h, float* __restrict__ agg, int N)
{
    int warp = (blockIdx.x * blockDim.x + threadIdx.x) >> 5;
    int lane = threadIdx.x & 31;
    if (warp >= N) return;
    int start = row_start[warp];
    int end   = row_start[warp + 1];
    float4 acc = make_float4(0.f, 0.f, 0.f, 0.f);
    int j = start;
    for (; j + 1 < end; j += 2) {
        int s0 = __ldg(&csr[j]);
        int s1 = __ldg(&csr[j + 1]);
        float4 v0 = *(const float4*)(h + (size_t)s0 * 128 + lane * 4);
        float4 v1 = *(const float4*)(h + (size_t)s1 * 128 + lane * 4);
        acc.x += v0.x + v1.x;
        acc.y += v0.y + v1.y;
        acc.z += v0.z + v1.z;
        acc.w += v0.w + v1.w;
    }
    if (j < end) {
        int s0 = __ldg(&csr[j]);
        float4 v0 = *(const float4*)(h + (size_t)s0 * 128 + lane * 4);
        acc.x += v0.x; acc.y += v0.y; acc.z += v0.z; acc.w += v0.w;
    }
    *(float4*)(agg + (size_t)warp * 128 + lane * 4) = acc;
}

__global__ __launch_bounds__(256)
void gather64(const int* __restrict__ row_start, const int* __restrict__ csr,
              const float* __restrict__ h, float* __restrict__ agg, int N)
{
    int warp = (blockIdx.x * blockDim.x + threadIdx.x) >> 5;
    int lane = threadIdx.x & 31;
    if (warp >= N) return;
    int start = row_start[warp];
    int end   = row_start[warp + 1];
    float2 acc = make_float2(0.f, 0.f);
    int j = start;
    for (; j + 1 < end; j += 2) {
        int s0 = __ldg(&csr[j]);
        int s1 = __ldg(&csr[j + 1]);
        float2 v0 = *(const float2*)(h + (size_t)s0 * 64 + lane * 2);
        float2 v1 = *(const float2*)(h + (size_t)s1 * 64 + lane * 2);
        acc.x += v0.x + v1.x;
        acc.y += v0.y + v1.y;
    }
    if (j < end) {
        int s0 = __ldg(&csr[j]);
        float2 v0 = *(const float2*)(h + (size_t)s0 * 64 + lane * 2);
        acc.x += v0.x; acc.y += v0.y;
    }
    *(float2*)(agg + (size_t)warp * 64 + lane * 2) = acc;
}

// ---------------------------------------------------------------------------
// Final epilogue: out = lrelu(agg * rs_in + b2), F = 64
// ---------------------------------------------------------------------------
__global__ void epilogue_kernel(const float* __restrict__ agg, const float* __restrict__ rs_in,
                                const float* __restrict__ b, float* __restrict__ out, int N)
{
    int idx = blockIdx.x * blockDim.x + threadIdx.x;
    int total = N * 16;
    if (idx >= total) return;
    int row = idx >> 4;
    int c = (idx & 15) * 4;
    float ri = rs_in[row];
    float4 v = *(const float4*)(agg + (size_t)row * 64 + c);
    v.x = lrelu(fmaf(v.x, ri, b[c + 0]));
    v.y = lrelu(fmaf(v.y, ri, b[c + 1]));
    v.z = lrelu(fmaf(v.z, ri, b[c + 2]));
    v.w = lrelu(fmaf(v.w, ri, b[c + 3]));
    *(float4*)(out + (size_t)row * 64 + c) = v;
}

// ---------------------------------------------------------------------------
// Launch
// ---------------------------------------------------------------------------
static inline int cdiv(int a, int b) { return (a + b - 1) / b; }

extern "C" void kernel_launch(void* const* d_in, const int* in_sizes, int n_in,
                              void* d_out, int out_size)
{
    const float* n_feat = (const float*)d_in[0];
    const int*   src    = (const int*)  d_in[1];
    const int*   dst    = (const int*)  d_in[2];
    const float* W0     = (const float*)d_in[3];
    const float* b0     = (const float*)d_in[4];
    const float* W1     = (const float*)d_in[5];
    const float* b1     = (const float*)d_in[6];
    const float* W2     = (const float*)d_in[7];
    const float* b2     = (const float*)d_in[8];
    float* out = (float*)d_out;

    const int N = in_sizes[0] / 128;
    const int E = in_sizes[1];

    float *d_h, *d_agg, *d_rso, *d_rsi;
    int *d_indeg, *d_excl, *d_rs, *d_cur, *d_csr, *d_bsum;
    uint32_t *d_bth, *d_btl;
    cudaGetSymbolAddress((void**)&d_h,    g_h);
    cudaGetSymbolAddress((void**)&d_agg,  g_agg);
    cudaGetSymbolAddress((void**)&d_rso,  g_rs_out);
    cudaGetSymbolAddress((void**)&d_rsi,  g_rs_in);
    cudaGetSymbolAddress((void**)&d_indeg, g_indeg);
    cudaGetSymbolAddress((void**)&d_excl, g_excl);
    cudaGetSymbolAddress((void**)&d_rs,   g_row_start);
    cudaGetSymbolAddress((void**)&d_cur,  g_cursor);
    cudaGetSymbolAddress((void**)&d_csr,  g_csr_src);
    cudaGetSymbolAddress((void**)&d_bsum, g_bsum);
    cudaGetSymbolAddress((void**)&d_bth,  g_bt_hi);
    cudaGetSymbolAddress((void**)&d_btl,  g_bt_lo);

    constexpr int SMEM_128 = (2 * 128 + 2 * 128) * 36 * 4;  // 73728
    constexpr int SMEM_64  = (2 * 128 + 2 * 64) * 36 * 4;   // 55296
    static bool attr_done = false;
    if (!attr_done) {
        cudaFuncSetAttribute(gemm_mma<128, 128, true>,
                             cudaFuncAttributeMaxDynamicSharedMemorySize, SMEM_128);
        cudaFuncSetAttribute(gemm_mma<128, 64, false>,
                             cudaFuncAttributeMaxDynamicSharedMemorySize, SMEM_64);
        cudaFuncSetAttribute(gemm_mma<64, 64, false>,
                             cudaFuncAttributeMaxDynamicSharedMemorySize, SMEM_64);
        attr_done = true;
    }

    // --- degrees ---
    cudaMemsetAsync(d_rso, 0, (size_t)N * sizeof(float));
    cudaMemsetAsync(d_indeg, 0, (size_t)N * sizeof(int));
    deg_kernel<<<cdiv(E, 256), 256>>>(src, dst, d_rso, d_indeg, E);
    rsqrt_kernel<<<cdiv(N, 256), 256>>>(d_rso, d_indeg, d_rsi, N);

    // --- CSR build ---
    const int nb = cdiv(N, 1024);
    scan_block<<<nb, 256>>>(d_indeg, d_excl, d_bsum, N);
    scan_bsum<<<1, 512>>>(d_bsum, nb);
    scan_add<<<cdiv(N, 256), 256>>>(d_excl, d_bsum, d_rs, d_cur, N, E);
    fill_csr<<<cdiv(E, 256), 256>>>(src, dst, d_cur, d_csr, E);

    const int gemm_blocks = cdiv(N, 128);
    const int gw_blocks = cdiv(N, 8);

    // --- layer 0: 128 -> 128 ---
    split_w<<<cdiv(128 * 128, 256), 256>>>(W0, d_bth, d_btl, 128, 128);
    gemm_mma<128, 128, true><<<gemm_blocks, 256, SMEM_128>>>(
        n_feat, d_bth, d_btl, nullptr, d_rso, d_rsi, d_h, N);
    gather128<<<gw_blocks, 256>>>(d_rs, d_csr, d_h, d_agg, N);

    // --- layer 1: 128 -> 64 ---
    split_w<<<cdiv(128 * 64, 256), 256>>>(W1, d_bth, d_btl, 128, 64);
    gemm_mma<128, 64, false><<<gemm_blocks, 256, SMEM_64>>>(
        d_agg, d_bth, d_btl, b0, d_rso, d_rsi, d_h, N);
    gather64<<<gw_blocks, 256>>>(d_rs, d_csr, d_h, d_agg, N);

    // --- layer 2: 64 -> 64 ---
    split_w<<<cdiv(64 * 64, 256), 256>>>(W2, d_bth, d_btl, 64, 64);
    gemm_mma<64, 64, false><<<gemm_blocks, 256, SMEM_64>>>(
        d_agg, d_bth, d_btl, b1, d_rso, d_rsi, d_h, N);
    gather64<<<gw_blocks, 256>>>(d_rs, d_csr, d_h, d_agg, N);

    // --- final epilogue ---
    epilogue_kernel<<<cdiv(N * 16, 256), 256>>>(d_agg, d_rsi, b2, out, N);
}